// round 9
// baseline (speedup 1.0000x reference)
#include <cuda_runtime.h>

// HomographyNet via Cayley-Hamilton.
// C = [ v4   v2   v0 ]      (traceless, sl(3))
//     [ v3  -v4-v5 v1 ]
//     [ v6   v7   v5 ]
// C^3 = p*C + q*I,  p = tr(C^2)/2,  q = det(C)
// => sum_{i=0..9} C^i/i! = a(p,q)*I + b(p,q)*C + c(p,q)*C^2   (exact degree-9 expansion)

__device__ __forceinline__ void expm3x3_ch(const float vv[8], float H[9]) {
    const float c00 = vv[4], c01 = vv[2], c02 = vv[0];
    const float c10 = vv[3], c11 = -vv[4] - vv[5], c12 = vv[1];
    const float c20 = vv[6], c21 = vv[7], c22 = vv[5];

    // D = C^2
    const float d00 = fmaf(c02, c20, fmaf(c01, c10, c00 * c00));
    const float d01 = fmaf(c02, c21, fmaf(c01, c11, c00 * c01));
    const float d02 = fmaf(c02, c22, fmaf(c01, c12, c00 * c02));
    const float d10 = fmaf(c12, c20, fmaf(c11, c10, c10 * c00));
    const float d11 = fmaf(c12, c21, fmaf(c11, c11, c10 * c01));
    const float d12 = fmaf(c12, c22, fmaf(c11, c12, c10 * c02));
    const float d20 = fmaf(c22, c20, fmaf(c21, c10, c20 * c00));
    const float d21 = fmaf(c22, c21, fmaf(c21, c11, c20 * c01));
    const float d22 = fmaf(c22, c22, fmaf(c21, c12, c20 * c02));

    // invariants
    const float p = 0.5f * (d00 + d11 + d22);          // tr(C^2)/2
    const float q = fmaf(c00, fmaf(c11, c22, -c12 * c21),
                   fmaf(-c01, fmaf(c10, c22, -c12 * c20),
                         c02 * fmaf(c10, c21, -c11 * c20)));  // det(C)

    // monomials
    const float p2  = p * p;
    const float q2  = q * q;
    const float pq  = p * q;
    const float p3  = p2 * p;
    const float p4  = p2 * p2;
    const float q3  = q * q2;
    const float p2q = p2 * q;
    const float pq2 = p * q2;
    const float p3q = p3 * q;

    float a = 1.0f;
    a = fmaf(q,   1.0f / 6.0f,      a);
    a = fmaf(pq,  1.0f / 120.0f,    a);
    a = fmaf(q2,  1.0f / 720.0f,    a);
    a = fmaf(p2q, 1.0f / 5040.0f,   a);
    a = fmaf(pq2, 1.0f / 20160.0f,  a);
    a = fmaf(q3,  1.0f / 362880.0f, a);
    a = fmaf(p3q, 1.0f / 362880.0f, a);

    float b = 1.0f;
    b = fmaf(p,   1.0f / 6.0f,      b);
    b = fmaf(q,   1.0f / 24.0f,     b);
    b = fmaf(p2,  1.0f / 120.0f,    b);
    b = fmaf(pq,  1.0f / 360.0f,    b);
    b = fmaf(q2,  1.0f / 5040.0f,   b);
    b = fmaf(p3,  1.0f / 5040.0f,   b);
    b = fmaf(p2q, 1.0f / 13440.0f,  b);
    b = fmaf(pq2, 1.0f / 120960.0f, b);
    b = fmaf(p4,  1.0f / 362880.0f, b);

    float c = 0.5f;
    c = fmaf(p,   1.0f / 24.0f,     c);
    c = fmaf(q,   1.0f / 120.0f,    c);
    c = fmaf(p2,  1.0f / 720.0f,    c);
    c = fmaf(pq,  1.0f / 2520.0f,   c);
    c = fmaf(q2,  1.0f / 40320.0f,  c);
    c = fmaf(p3,  1.0f / 40320.0f,  c);
    c = fmaf(p2q, 1.0f / 120960.0f, c);

    // H = a*I + b*C + c*C^2
    H[0] = fmaf(b, c00, fmaf(c, d00, a));
    H[1] = fmaf(b, c01, c * d01);
    H[2] = fmaf(b, c02, c * d02);
    H[3] = fmaf(b, c10, c * d10);
    H[4] = fmaf(b, c11, fmaf(c, d11, a));
    H[5] = fmaf(b, c12, c * d12);
    H[6] = fmaf(b, c20, c * d20);
    H[7] = fmaf(b, c21, c * d21);
    H[8] = fmaf(b, c22, fmaf(c, d22, a));
}

// Warp-autonomous staging: each warp owns 64 items and a private 2304B smem
// slab; it computes, stages (stride-9 STS, conflict-free), __syncwarp()s, and
// drains its own slab with coalesced LDS.128+STG.128. No block barrier ->
// warps pipeline independently (loads of one warp overlap stores of another).
// 512 items/block (8 warps x 64), 2 items/thread, front-batched loads (MLP=4).
__global__ __launch_bounds__(256)
void homography_expm_kernel(const float4* __restrict__ v4,
                            float4* __restrict__ o4,
                            float* __restrict__ o,
                            int n)
{
    __shared__ __align__(16) float s[8][576];   // per-warp slab: 64 items * 9 floats

    const unsigned tid  = threadIdx.x;
    const unsigned wid  = tid >> 5;
    const unsigned lane = tid & 31u;

    const unsigned gbase = blockIdx.x * 512u + wid * 64u;   // warp's first item
    const unsigned iA = gbase + lane;
    const unsigned iB = gbase + 32u + lane;

    float* sw = s[wid];

    if (iB < (unsigned)n) {
        // fast path: both items valid — batch all 4 loads (MLP=4)
        const float4 a0 = __ldcs(v4 + iA * 2u);
        const float4 a1 = __ldcs(v4 + iA * 2u + 1u);
        const float4 b0 = __ldcs(v4 + iB * 2u);
        const float4 b1 = __ldcs(v4 + iB * 2u + 1u);

        float vA[8] = {a0.x, a0.y, a0.z, a0.w, a1.x, a1.y, a1.z, a1.w};
        float HA[9];
        expm3x3_ch(vA, HA);
#pragma unroll
        for (int k = 0; k < 9; k++) sw[lane * 9u + k] = HA[k];

        float vB[8] = {b0.x, b0.y, b0.z, b0.w, b1.x, b1.y, b1.z, b1.w};
        float HB[9];
        expm3x3_ch(vB, HB);
#pragma unroll
        for (int k = 0; k < 9; k++) sw[(32u + lane) * 9u + k] = HB[k];
    } else if (iA < (unsigned)n) {
        const float4 a0 = __ldcs(v4 + iA * 2u);
        const float4 a1 = __ldcs(v4 + iA * 2u + 1u);
        float vA[8] = {a0.x, a0.y, a0.z, a0.w, a1.x, a1.y, a1.z, a1.w};
        float HA[9];
        expm3x3_ch(vA, HA);
#pragma unroll
        for (int k = 0; k < 9; k++) sw[lane * 9u + k] = HA[k];
    }
    __syncwarp();

    if (gbase + 64u <= (unsigned)n) {
        // full warp group: 144 coalesced float4 stores by the owning warp
        const float4* sf = reinterpret_cast<const float4*>(sw);
        float4* dst = o4 + gbase * 9u / 4u;     // gbase multiple of 64 -> exact
#pragma unroll
        for (unsigned i = 0; i < 4; i++)
            __stcs(dst + lane + 32u * i, sf[lane + 32u * i]);
        if (lane < 16u) __stcs(dst + lane + 128u, sf[lane + 128u]);
    } else if (gbase < (unsigned)n) {
        // tail group: guarded coalesced scalar copy
        const unsigned total = ((unsigned)n - gbase) * 9u;
        float* dst = o + gbase * 9u;
        for (unsigned idx = lane; idx < total; idx += 32u) dst[idx] = sw[idx];
    }
}

extern "C" void kernel_launch(void* const* d_in, const int* in_sizes, int n_in,
                              void* d_out, int out_size)
{
    const float* v = (const float*)d_in[0];
    float* o = (float*)d_out;
    const int n = in_sizes[0] / 8;
    const int grid = (n + 511) / 512;
    homography_expm_kernel<<<grid, 256>>>(
        (const float4*)v, (float4*)o, o, n);
}